// round 14
// baseline (speedup 1.0000x reference)
#include <cuda_runtime.h>
#include <cstdint>

// GaussianRP: x (8,16,32,1024) f32, log_sigma scalar f32
// out (8,16,1024,1024) f32:
//   rp[b,c,t,s] = exp(-max(|x_t|^2+|x_s|^2-2<x_t,x_s>, 0) / (2 sigma^2))
//
// Round 14 (= R13 resubmit; R13 never ran due to infra): champion 3xTF32
// mma.sync kernel with the offdiag transposed store routed through a padded
// smem tile: scalar STS transposed (conflict-free banks) -> sync -> row-wise
// LDS.128 -> coalesced STG.128. Replaces 16 scattered STG.32/thread.
// TR_PITCH=68 (multiple of 4) so every Tr row is 16B-aligned.

#define NDIM  32
#define NT    1024
#define NBC   128

#define TILE  64
#define NTILE (NT / TILE)                  // 16
#define NPAIR (NTILE * (NTILE + 1) / 2)    // 136

#define TWORDS 2048                        // fragment words per (bc,tile)
#define FR_TOT (NBC * NTILE * TWORDS)      // 4,194,304 per array
#define NORM_N (NBC * NT)                  // 131072

#define TR_PITCH 68                        // 64 + 4 pad: 16B-aligned rows

__device__ float g_sqnorm[NBC * NT];
__device__ float g_scale;   // 1/(2 sigma^2)

__device__ float g_Ahi[FR_TOT];
__device__ float g_Alo[FR_TOT];
__device__ float g_Bhi[FR_TOT];
__device__ float g_Blo[FR_TOT];

__device__ __forceinline__ uint32_t f2tf32(float v) {
    uint32_t r;
    asm("cvt.rna.tf32.f32 %0, %1;" : "=r"(r) : "f"(v));
    return r;
}

// Combined prologue: A-frag pack | B-frag pack | sqnorms (+g_scale).
__global__ __launch_bounds__(256)
void prologue_kernel(const float* __restrict__ x,
                     const float* __restrict__ log_sigma) {
    int idx = blockIdx.x * blockDim.x + threadIdx.x;
    if (idx < FR_TOT) {
        int w    = idx;
        int idxA = w & 3;
        int lane = (w >> 2) & 31;
        int ks   = (w >> 7) & 3;
        int ms   = (w >> 9) & 3;
        int tile = (w >> 11) & 15;
        int bc   = w >> 15;
        int tl   = ms * 16 + ((idxA >> 1) & 1) * 8 + (lane >> 2);
        int k    = ks * 8 + (idxA & 1) * 4 + (lane & 3);
        float v  = x[(size_t)bc * NDIM * NT + k * NT + tile * TILE + tl];
        float hf = __uint_as_float(f2tf32(v));
        g_Ahi[w] = hf;
        g_Alo[w] = __uint_as_float(f2tf32(v - hf));
    } else if (idx < 2 * FR_TOT) {
        int w    = idx - FR_TOT;
        int idxB = w & 1;
        int lane = (w >> 1) & 31;
        int ks   = (w >> 6) & 3;
        int nb   = (w >> 8) & 7;
        int tile = (w >> 11) & 15;
        int bc   = w >> 15;
        int sl   = nb * 8 + (lane >> 2);
        int k    = ks * 8 + idxB * 4 + (lane & 3);
        float v  = x[(size_t)bc * NDIM * NT + k * NT + tile * TILE + sl];
        float hf = __uint_as_float(f2tf32(v));
        g_Bhi[w] = hf;
        g_Blo[w] = __uint_as_float(f2tf32(v - hf));
    } else if (idx < 2 * FR_TOT + NORM_N) {
        int n = idx - 2 * FR_TOT;
        if (n == 0) g_scale = 0.5f * __expf(-2.f * log_sigma[0]);
        int bc = n >> 10;
        int t  = n & (NT - 1);
        const float* p = x + (size_t)bc * NDIM * NT + t;
        float s = 0.f;
#pragma unroll
        for (int d = 0; d < NDIM; ++d) {
            float v = p[d * NT];
            s = fmaf(v, v, s);
        }
        g_sqnorm[n] = s;
    }
}

__device__ __forceinline__ void mma_tf32(float d[4],
                                         uint32_t a0, uint32_t a1,
                                         uint32_t a2, uint32_t a3,
                                         uint32_t b0, uint32_t b1) {
    asm volatile(
        "mma.sync.aligned.m16n8k8.row.col.f32.tf32.tf32.f32 "
        "{%0,%1,%2,%3}, {%4,%5,%6,%7}, {%8,%9}, {%0,%1,%2,%3};"
        : "+f"(d[0]), "+f"(d[1]), "+f"(d[2]), "+f"(d[3])
        : "r"(a0), "r"(a1), "r"(a2), "r"(a3), "r"(b0), "r"(b1));
}

__global__ __launch_bounds__(256, 3)
void gaussian_rp_mma(float* __restrict__ out) {
    // transposed staging tile: Tr[scol][trow]
    __shared__ __align__(16) float Tr[TILE][TR_PITCH];

    const int p  = blockIdx.x;        // pair fastest -> L2 locality per bc
    const int bc = blockIdx.y;

    int ss = 0;
#pragma unroll
    for (int c = 1; c < NTILE; ++c)
        ss += (p >= c * (c + 1) / 2) ? 1 : 0;
    const int ts = p - ss * (ss + 1) / 2;
    const int t0 = ts * TILE;
    const int s0 = ss * TILE;

    const int tid  = threadIdx.x;
    const int lane = tid & 31;
    const int wid  = tid >> 5;        // 0..7
    const int wm   = wid & 1;          // t half (32 rows)
    const int wn   = wid >> 1;         // s quarter (16 cols)
    const int g    = lane >> 2;
    const int tig  = lane & 3;

    const uint32_t* __restrict__ Ahi =
        (const uint32_t*)g_Ahi + (size_t)(bc * NTILE + ts) * TWORDS;
    const uint32_t* __restrict__ Alo =
        (const uint32_t*)g_Alo + (size_t)(bc * NTILE + ts) * TWORDS;
    const uint32_t* __restrict__ Bhi =
        (const uint32_t*)g_Bhi + (size_t)(bc * NTILE + ss) * TWORDS;
    const uint32_t* __restrict__ Blo =
        (const uint32_t*)g_Blo + (size_t)(bc * NTILE + ss) * TWORDS;

    float acc[2][2][4];
#pragma unroll
    for (int i = 0; i < 2; ++i)
#pragma unroll
        for (int j = 0; j < 2; ++j)
#pragma unroll
            for (int q = 0; q < 4; ++q) acc[i][j][q] = 0.f;

#pragma unroll
    for (int kk = 0; kk < 4; ++kk) {
        uint4 fh[2], fl[2];
#pragma unroll
        for (int msi = 0; msi < 2; ++msi) {
            int off = (((wm * 2 + msi) * 4 + kk) * 32 + lane) * 4;
            fh[msi] = *(const uint4*)(Ahi + off);
            fl[msi] = *(const uint4*)(Alo + off);
        }
#pragma unroll
        for (int nbl = 0; nbl < 2; ++nbl) {
            int boff = (((wn * 2 + nbl) * 4 + kk) * 32 + lane) * 2;
            uint2 bh = *(const uint2*)(Bhi + boff);
            uint2 bl = *(const uint2*)(Blo + boff);
#pragma unroll
            for (int msi = 0; msi < 2; ++msi) {
                // stored order [a0,a2,a1,a3] -> operands (a0,a1,a2,a3)
                mma_tf32(acc[msi][nbl], fh[msi].x, fh[msi].z, fh[msi].y, fh[msi].w, bh.x, bh.y); // hi*hi
                mma_tf32(acc[msi][nbl], fl[msi].x, fl[msi].z, fl[msi].y, fl[msi].w, bh.x, bh.y); // lo*hi
                mma_tf32(acc[msi][nbl], fh[msi].x, fh[msi].z, fh[msi].y, fh[msi].w, bl.x, bl.y); // hi*lo
            }
        }
    }

    // ---- epilogue: d2 -> exp ----
    const float scale  = g_scale;
    const float scale2 = 2.f * scale;
    const float* sq = &g_sqnorm[bc * NT];

    float snt[2][2], sns[2][2];
#pragma unroll
    for (int msi = 0; msi < 2; ++msi) {
        int tl = wm * 32 + msi * 16 + g;
        snt[msi][0] = scale * sq[t0 + tl];
        snt[msi][1] = scale * sq[t0 + tl + 8];
    }
#pragma unroll
    for (int nbl = 0; nbl < 2; ++nbl) {
        int sl = wn * 16 + nbl * 8 + 2 * tig;
        sns[nbl][0] = scale * sq[s0 + sl];
        sns[nbl][1] = scale * sq[s0 + sl + 1];
    }

    float* ob = out + (size_t)bc * NT * NT;
    const bool offdiag = (ts != ss);

#pragma unroll
    for (int msi = 0; msi < 2; ++msi) {
#pragma unroll
        for (int nbl = 0; nbl < 2; ++nbl) {
            float* d = acc[msi][nbl];
            float r0 = __expf(fminf(fmaf(scale2, d[0], -(snt[msi][0] + sns[nbl][0])), 0.f));
            float r1 = __expf(fminf(fmaf(scale2, d[1], -(snt[msi][0] + sns[nbl][1])), 0.f));
            float r2 = __expf(fminf(fmaf(scale2, d[2], -(snt[msi][1] + sns[nbl][0])), 0.f));
            float r3 = __expf(fminf(fmaf(scale2, d[3], -(snt[msi][1] + sns[nbl][1])), 0.f));

            int tl = wm * 32 + msi * 16 + g;
            int sl = wn * 16 + nbl * 8 + 2 * tig;

            // normal tile: rows t, contiguous (s,s+1) pairs
            *(float2*)(ob + (size_t)(t0 + tl) * NT + s0 + sl)     = make_float2(r0, r1);
            *(float2*)(ob + (size_t)(t0 + tl + 8) * NT + s0 + sl) = make_float2(r2, r3);

            // stage transposed into smem (conflict-free scalar STS:
            // bank = (4*sl + tl) mod 32 = 8*tig + g + const, distinct/warp)
            if (offdiag) {
                Tr[sl][tl]         = r0;
                Tr[sl + 1][tl]     = r1;
                Tr[sl][tl + 8]     = r2;
                Tr[sl + 1][tl + 8] = r3;
            }
        }
    }

    if (offdiag) {
        __syncthreads();
        // read rows of Tr (contiguous t) and store coalesced:
        // thread -> s-row tid/4, t-chunk (tid%4)*16 (4x float4)
        const int srow  = tid >> 2;
        const int tbase = (tid & 3) * 16;
        float* dst = ob + (size_t)(s0 + srow) * NT + t0 + tbase;
        const float* src = &Tr[srow][tbase];
#pragma unroll
        for (int q = 0; q < 4; ++q) {
            float4 v = *(const float4*)(src + q * 4);
            *(float4*)(dst + q * 4) = v;
        }
    }
}

extern "C" void kernel_launch(void* const* d_in, const int* in_sizes, int n_in,
                              void* d_out, int out_size) {
    const float* x  = (const float*)d_in[0];
    const float* ls = (const float*)d_in[1];
    float* out      = (float*)d_out;

    int prologue_threads = 2 * FR_TOT + NORM_N;
    prologue_kernel<<<(prologue_threads + 255) / 256, 256>>>(x, ls);

    dim3 grid(NPAIR, NBC);
    gaussian_rp_mma<<<grid, 256>>>(out);
}

// round 15
// speedup vs baseline: 1.3271x; 1.3271x over previous
#include <cuda_runtime.h>
#include <cstdint>

// GaussianRP: x (8,16,32,1024) f32, log_sigma scalar f32
// out (8,16,1024,1024) f32:
//   rp[b,c,t,s] = exp(-max(|x_t|^2+|x_s|^2-2<x_t,x_s>, 0) / (2 sigma^2))
//
// Round 15: smem-transpose REVERTED (R14 showed LDS/STS share the L1 pipe and
// made it worse). Fragment-traffic cut instead: 64x64 tile with 128 threads /
// 4 warps, each warp a 32x32 sub-tile (2 msi x 4 nbl) -> fragment bytes per
// output drop 24B -> 16B and A-fragment cross-warp redundancy 4x -> 2x.
// Direct scattered stores for the transposed tile (R11 epilogue).
// 3xTF32 mma.sync, pre-packed fragments (layout unchanged), pair-fastest
// grid, merged prologue.

#define NDIM  32
#define NT    1024
#define NBC   128

#define TILE  64
#define NTILE (NT / TILE)                  // 16
#define NPAIR (NTILE * (NTILE + 1) / 2)    // 136

#define TWORDS 2048                        // fragment words per (bc,tile)
#define FR_TOT (NBC * NTILE * TWORDS)      // 4,194,304 per array
#define NORM_N (NBC * NT)                  // 131072

__device__ float g_sqnorm[NBC * NT];
__device__ float g_scale;   // 1/(2 sigma^2)

__device__ float g_Ahi[FR_TOT];
__device__ float g_Alo[FR_TOT];
__device__ float g_Bhi[FR_TOT];
__device__ float g_Blo[FR_TOT];

__device__ __forceinline__ uint32_t f2tf32(float v) {
    uint32_t r;
    asm("cvt.rna.tf32.f32 %0, %1;" : "=r"(r) : "f"(v));
    return r;
}

// Combined prologue: A-frag pack | B-frag pack | sqnorms (+g_scale).
__global__ __launch_bounds__(256)
void prologue_kernel(const float* __restrict__ x,
                     const float* __restrict__ log_sigma) {
    int idx = blockIdx.x * blockDim.x + threadIdx.x;
    if (idx < FR_TOT) {
        int w    = idx;
        int idxA = w & 3;
        int lane = (w >> 2) & 31;
        int ks   = (w >> 7) & 3;
        int ms   = (w >> 9) & 3;
        int tile = (w >> 11) & 15;
        int bc   = w >> 15;
        int tl   = ms * 16 + ((idxA >> 1) & 1) * 8 + (lane >> 2);
        int k    = ks * 8 + (idxA & 1) * 4 + (lane & 3);
        float v  = x[(size_t)bc * NDIM * NT + k * NT + tile * TILE + tl];
        float hf = __uint_as_float(f2tf32(v));
        g_Ahi[w] = hf;
        g_Alo[w] = __uint_as_float(f2tf32(v - hf));
    } else if (idx < 2 * FR_TOT) {
        int w    = idx - FR_TOT;
        int idxB = w & 1;
        int lane = (w >> 1) & 31;
        int ks   = (w >> 6) & 3;
        int nb   = (w >> 8) & 7;
        int tile = (w >> 11) & 15;
        int bc   = w >> 15;
        int sl   = nb * 8 + (lane >> 2);
        int k    = ks * 8 + idxB * 4 + (lane & 3);
        float v  = x[(size_t)bc * NDIM * NT + k * NT + tile * TILE + sl];
        float hf = __uint_as_float(f2tf32(v));
        g_Bhi[w] = hf;
        g_Blo[w] = __uint_as_float(f2tf32(v - hf));
    } else if (idx < 2 * FR_TOT + NORM_N) {
        int n = idx - 2 * FR_TOT;
        if (n == 0) g_scale = 0.5f * __expf(-2.f * log_sigma[0]);
        int bc = n >> 10;
        int t  = n & (NT - 1);
        const float* p = x + (size_t)bc * NDIM * NT + t;
        float s = 0.f;
#pragma unroll
        for (int d = 0; d < NDIM; ++d) {
            float v = p[d * NT];
            s = fmaf(v, v, s);
        }
        g_sqnorm[n] = s;
    }
}

__device__ __forceinline__ void mma_tf32(float d[4],
                                         uint32_t a0, uint32_t a1,
                                         uint32_t a2, uint32_t a3,
                                         uint32_t b0, uint32_t b1) {
    asm volatile(
        "mma.sync.aligned.m16n8k8.row.col.f32.tf32.tf32.f32 "
        "{%0,%1,%2,%3}, {%4,%5,%6,%7}, {%8,%9}, {%0,%1,%2,%3};"
        : "+f"(d[0]), "+f"(d[1]), "+f"(d[2]), "+f"(d[3])
        : "r"(a0), "r"(a1), "r"(a2), "r"(a3), "r"(b0), "r"(b1));
}

__global__ __launch_bounds__(128, 5)
void gaussian_rp_mma(float* __restrict__ out) {
    const int p  = blockIdx.x;        // pair fastest -> L2 locality per bc
    const int bc = blockIdx.y;

    int ss = 0;
#pragma unroll
    for (int c = 1; c < NTILE; ++c)
        ss += (p >= c * (c + 1) / 2) ? 1 : 0;
    const int ts = p - ss * (ss + 1) / 2;
    const int t0 = ts * TILE;
    const int s0 = ss * TILE;

    const int tid  = threadIdx.x;
    const int lane = tid & 31;
    const int wid  = tid >> 5;        // 0..3
    const int wm   = wid & 1;          // t half (32 rows)
    const int wn   = wid >> 1;         // s half (32 cols)
    const int g    = lane >> 2;
    const int tig  = lane & 3;

    const uint32_t* __restrict__ Ahi =
        (const uint32_t*)g_Ahi + (size_t)(bc * NTILE + ts) * TWORDS;
    const uint32_t* __restrict__ Alo =
        (const uint32_t*)g_Alo + (size_t)(bc * NTILE + ts) * TWORDS;
    const uint32_t* __restrict__ Bhi =
        (const uint32_t*)g_Bhi + (size_t)(bc * NTILE + ss) * TWORDS;
    const uint32_t* __restrict__ Blo =
        (const uint32_t*)g_Blo + (size_t)(bc * NTILE + ss) * TWORDS;

    // warp tile: 32(t) x 32(s) = 2 msi x 4 nbl
    float acc[2][4][4];
#pragma unroll
    for (int i = 0; i < 2; ++i)
#pragma unroll
        for (int j = 0; j < 4; ++j)
#pragma unroll
            for (int q = 0; q < 4; ++q) acc[i][j][q] = 0.f;

#pragma unroll
    for (int kk = 0; kk < 4; ++kk) {
        uint4 fh[2], fl[2];
#pragma unroll
        for (int msi = 0; msi < 2; ++msi) {
            int off = (((wm * 2 + msi) * 4 + kk) * 32 + lane) * 4;
            fh[msi] = *(const uint4*)(Ahi + off);
            fl[msi] = *(const uint4*)(Alo + off);
        }
#pragma unroll
        for (int nbl = 0; nbl < 4; ++nbl) {
            int boff = (((wn * 4 + nbl) * 4 + kk) * 32 + lane) * 2;
            uint2 bh = *(const uint2*)(Bhi + boff);
            uint2 bl = *(const uint2*)(Blo + boff);
#pragma unroll
            for (int msi = 0; msi < 2; ++msi) {
                // stored order [a0,a2,a1,a3] -> operands (a0,a1,a2,a3)
                mma_tf32(acc[msi][nbl], fh[msi].x, fh[msi].z, fh[msi].y, fh[msi].w, bh.x, bh.y); // hi*hi
                mma_tf32(acc[msi][nbl], fl[msi].x, fl[msi].z, fl[msi].y, fl[msi].w, bh.x, bh.y); // lo*hi
                mma_tf32(acc[msi][nbl], fh[msi].x, fh[msi].z, fh[msi].y, fh[msi].w, bl.x, bl.y); // hi*lo
            }
        }
    }

    // ---- epilogue: d2 -> exp -> dual store ----
    const float scale  = g_scale;
    const float scale2 = 2.f * scale;
    const float* sq = &g_sqnorm[bc * NT];

    float snt[2][2], sns[4][2];
#pragma unroll
    for (int msi = 0; msi < 2; ++msi) {
        int tl = wm * 32 + msi * 16 + g;
        snt[msi][0] = scale * sq[t0 + tl];
        snt[msi][1] = scale * sq[t0 + tl + 8];
    }
#pragma unroll
    for (int nbl = 0; nbl < 4; ++nbl) {
        int sl = wn * 32 + nbl * 8 + 2 * tig;
        sns[nbl][0] = scale * sq[s0 + sl];
        sns[nbl][1] = scale * sq[s0 + sl + 1];
    }

    float* ob = out + (size_t)bc * NT * NT;
    const bool offdiag = (ts != ss);

#pragma unroll
    for (int msi = 0; msi < 2; ++msi) {
#pragma unroll
        for (int nbl = 0; nbl < 4; ++nbl) {
            float* d = acc[msi][nbl];
            float r0 = __expf(fminf(fmaf(scale2, d[0], -(snt[msi][0] + sns[nbl][0])), 0.f));
            float r1 = __expf(fminf(fmaf(scale2, d[1], -(snt[msi][0] + sns[nbl][1])), 0.f));
            float r2 = __expf(fminf(fmaf(scale2, d[2], -(snt[msi][1] + sns[nbl][0])), 0.f));
            float r3 = __expf(fminf(fmaf(scale2, d[3], -(snt[msi][1] + sns[nbl][1])), 0.f));

            int tl = wm * 32 + msi * 16 + g;
            int sl = wn * 32 + nbl * 8 + 2 * tig;

            // normal tile: rows t, contiguous (s,s+1) pairs
            *(float2*)(ob + (size_t)(t0 + tl) * NT + s0 + sl)     = make_float2(r0, r1);
            *(float2*)(ob + (size_t)(t0 + tl + 8) * NT + s0 + sl) = make_float2(r2, r3);

            // transposed tile: direct scattered stores (t runs 8-consecutive
            // per quad -> each instruction covers full 32B sectors)
            if (offdiag) {
                ob[(size_t)(s0 + sl)     * NT + t0 + tl]     = r0;
                ob[(size_t)(s0 + sl + 1) * NT + t0 + tl]     = r1;
                ob[(size_t)(s0 + sl)     * NT + t0 + tl + 8] = r2;
                ob[(size_t)(s0 + sl + 1) * NT + t0 + tl + 8] = r3;
            }
        }
    }
}

extern "C" void kernel_launch(void* const* d_in, const int* in_sizes, int n_in,
                              void* d_out, int out_size) {
    const float* x  = (const float*)d_in[0];
    const float* ls = (const float*)d_in[1];
    float* out      = (float*)d_out;

    int prologue_threads = 2 * FR_TOT + NORM_N;
    prologue_kernel<<<(prologue_threads + 255) / 256, 256>>>(x, ls);

    dim3 grid(NPAIR, NBC);
    gaussian_rp_mma<<<grid, 128>>>(out);
}